// round 2
// baseline (speedup 1.0000x reference)
#include <cuda_runtime.h>

// Segment-normalized 4x4 linear.
// Each segment is split into SPLIT equal chunks; one CTA per chunk (perfect
// load balance: max chunk ~ max_seg/SPLIT). Chunks of a segment cooperate:
//   pass 1: chunk-local sum of |y|, atomicAdd into g_seg_sum[s], arrive on
//           g_seg_cnt[s]; spin until all SPLIT partials have landed.
//   pass 2: recompute y from x (chunk is 8KB -> L1 hit) and scale by 1/sum.
// CTAs take a global atomic ticket so the launched-ticket set is an exact
// prefix -> at most one segment-group straddles the launch frontier -> no
// deadlock. Equal chunks arrive nearly simultaneously -> negligible spin.

#define NSEG_MAX 4096
#define SPLIT    4
#define BLOCK    256

__device__ float        g_seg_sum[NSEG_MAX];
__device__ unsigned int g_seg_cnt[NSEG_MAX];
__device__ unsigned int g_ticket;

__global__ void zero_kernel(int nseg)
{
    int i = blockIdx.x * blockDim.x + threadIdx.x;
    if (i < nseg) { g_seg_sum[i] = 0.0f; g_seg_cnt[i] = 0u; }
    if (i == 0) g_ticket = 0u;
}

__global__ __launch_bounds__(BLOCK)
void seg_norm_split(const float4* __restrict__ x,
                    const int*    __restrict__ slices,
                    const float*  __restrict__ W,
                    float4*       __restrict__ out,
                    int nseg)
{
    __shared__ unsigned int s_ticket;
    __shared__ float s_red[BLOCK / 32];
    __shared__ float s_inv;

    if (threadIdx.x == 0) s_ticket = atomicAdd(&g_ticket, 1u);
    __syncthreads();

    const unsigned int t = s_ticket;
    const int s = (int)(t / SPLIT);
    const int c = (int)(t % SPLIT);
    if (s >= nseg) return;

    const int lo  = slices[s];
    const int hi  = slices[s + 1];
    const int len = hi - lo;
    const int c_lo = lo + (int)(((long long)len * c)       / SPLIT);
    const int c_hi = lo + (int)(((long long)len * (c + 1)) / SPLIT);

    float w[16];
#pragma unroll
    for (int i = 0; i < 16; ++i) w[i] = __ldg(&W[i]);

    // ---- pass 1: chunk-local sum of |y| ----
    float local = 0.0f;
#pragma unroll 4
    for (int r = c_lo + (int)threadIdx.x; r < c_hi; r += BLOCK) {
        float4 v = x[r];
        float y0 = v.x * w[0]  + v.y * w[1]  + v.z * w[2]  + v.w * w[3];
        float y1 = v.x * w[4]  + v.y * w[5]  + v.z * w[6]  + v.w * w[7];
        float y2 = v.x * w[8]  + v.y * w[9]  + v.z * w[10] + v.w * w[11];
        float y3 = v.x * w[12] + v.y * w[13] + v.z * w[14] + v.w * w[15];
        local += fabsf(y0) + fabsf(y1) + fabsf(y2) + fabsf(y3);
    }

#pragma unroll
    for (int o = 16; o > 0; o >>= 1)
        local += __shfl_down_sync(0xFFFFFFFFu, local, o);

    const int lane = threadIdx.x & 31;
    const int warp = threadIdx.x >> 5;
    if (lane == 0) s_red[warp] = local;
    __syncthreads();

    // ---- cross-chunk combine: atomic sum + arrival count + spin ----
    if (threadIdx.x == 0) {
        float total = 0.0f;
#pragma unroll
        for (int i = 0; i < BLOCK / 32; ++i) total += s_red[i];

        atomicAdd(&g_seg_sum[s], total);
        __threadfence();                       // sum visible before arrival
        atomicAdd(&g_seg_cnt[s], 1u);

        while (((volatile unsigned int*)g_seg_cnt)[s] < (unsigned)SPLIT)
            __nanosleep(32);
        __threadfence();                       // acquire the final sum

        float tot = ((volatile float*)g_seg_sum)[s];
        s_inv = 1.0f / tot;                    // empty segment -> inf, 0 rows written
    }
    __syncthreads();
    const float inv = s_inv;

    // ---- pass 2: recompute (chunk x is L1-resident) and scale ----
#pragma unroll 4
    for (int r = c_lo + (int)threadIdx.x; r < c_hi; r += BLOCK) {
        float4 v = x[r];
        float4 o;
        o.x = (v.x * w[0]  + v.y * w[1]  + v.z * w[2]  + v.w * w[3])  * inv;
        o.y = (v.x * w[4]  + v.y * w[5]  + v.z * w[6]  + v.w * w[7])  * inv;
        o.z = (v.x * w[8]  + v.y * w[9]  + v.z * w[10] + v.w * w[11]) * inv;
        o.w = (v.x * w[12] + v.y * w[13] + v.z * w[14] + v.w * w[15]) * inv;
        out[r] = o;
    }
}

extern "C" void kernel_launch(void* const* d_in, const int* in_sizes, int n_in,
                              void* d_out, int out_size)
{
    const float4* x      = (const float4*)d_in[0];   // [N_ROWS, 4] fp32
    const int*    slices = (const int*)d_in[1];      // [nseg+1] int32
    const float*  W      = (const float*)d_in[2];    // [4, 4] fp32
    float4*       out    = (float4*)d_out;           // [N_ROWS, 4] fp32

    const int nseg = in_sizes[1] - 1;                // 4096

    zero_kernel<<<(nseg + 1023) / 1024, 1024>>>(nseg);
    seg_norm_split<<<nseg * SPLIT, BLOCK>>>(x, slices, W, out, nseg);
}

// round 3
// speedup vs baseline: 1.1153x; 1.1153x over previous
#include <cuda_runtime.h>
#include <cstdint>

// Segment-normalized 4x4 linear: y = x @ W^T, then y /= sum(|y|) per segment.
//
// One 4-CTA CLUSTER per segment; each CTA (rank) owns an equal 1/4 chunk.
//   pass 1: chunk-local sum of |y| -> smem s_partial
//   cluster barrier (HW co-scheduled, ~380cyc, release+acquire)
//   each CTA reads all 4 partials via DSMEM (mapa) -> inv = 1/total
//   pass 2: recompute y (chunk re-read hits L2) and write y * inv
// Equal chunks => zero skew at both barriers. No global state, no atomics,
// no spin, single launch, trivially graph-capturable.

#define SPLIT 4
#define BLOCK 256

__device__ __forceinline__ uint32_t smem_u32(const void* p) {
    uint32_t a;
    asm("{ .reg .u64 t; cvta.to.shared.u64 t, %1; cvt.u32.u64 %0, t; }"
        : "=r"(a) : "l"(p));
    return a;
}

__global__ __launch_bounds__(BLOCK) __cluster_dims__(SPLIT, 1, 1)
void seg_norm_cluster(const float4* __restrict__ x,
                      const int*    __restrict__ slices,
                      const float*  __restrict__ W,
                      float4*       __restrict__ out)
{
    __shared__ float s_partial;
    __shared__ float s_red[BLOCK / 32];
    __shared__ float s_inv;

    const int s = blockIdx.x / SPLIT;          // segment id (== cluster id)
    const int c = blockIdx.x % SPLIT;          // rank within cluster

    const int lo  = slices[s];
    const int hi  = slices[s + 1];
    const int len = hi - lo;
    const int c_lo = lo + (len * c)       / SPLIT;
    const int c_hi = lo + (len * (c + 1)) / SPLIT;

    float w[16];
#pragma unroll
    for (int i = 0; i < 16; ++i) w[i] = __ldg(&W[i]);

    // ---- pass 1: chunk-local sum of |y| ----
    float local = 0.0f;
#pragma unroll 4
    for (int r = c_lo + (int)threadIdx.x; r < c_hi; r += BLOCK) {
        float4 v = x[r];
        float y0 = v.x * w[0]  + v.y * w[1]  + v.z * w[2]  + v.w * w[3];
        float y1 = v.x * w[4]  + v.y * w[5]  + v.z * w[6]  + v.w * w[7];
        float y2 = v.x * w[8]  + v.y * w[9]  + v.z * w[10] + v.w * w[11];
        float y3 = v.x * w[12] + v.y * w[13] + v.z * w[14] + v.w * w[15];
        local += fabsf(y0) + fabsf(y1) + fabsf(y2) + fabsf(y3);
    }

#pragma unroll
    for (int o = 16; o > 0; o >>= 1)
        local += __shfl_down_sync(0xFFFFFFFFu, local, o);

    const int lane = threadIdx.x & 31;
    const int warp = threadIdx.x >> 5;
    if (lane == 0) s_red[warp] = local;
    __syncthreads();

    if (threadIdx.x == 0) {
        float t = 0.0f;
#pragma unroll
        for (int i = 0; i < BLOCK / 32; ++i) t += s_red[i];
        s_partial = t;                         // released by this thread's arrive
    }

    // ---- cluster barrier #1: all partials published ----
    asm volatile("barrier.cluster.arrive.aligned;" ::: "memory");
    asm volatile("barrier.cluster.wait.aligned;"   ::: "memory");

    // ---- gather 4 partials via DSMEM ----
    if (threadIdx.x == 0) {
        const uint32_t my = smem_u32(&s_partial);
        float tot = 0.0f;
#pragma unroll
        for (int t = 0; t < SPLIT; ++t) {
            uint32_t ra; float p;
            asm volatile("mapa.shared::cluster.u32 %0, %1, %2;"
                         : "=r"(ra) : "r"(my), "r"(t));
            asm volatile("ld.shared::cluster.f32 %0, [%1];"
                         : "=f"(p) : "r"(ra));
            tot += p;
        }
        s_inv = 1.0f / tot;                    // empty segment -> inf, 0 rows written
    }
    __syncthreads();
    const float inv = s_inv;

    // arrive for exit-barrier now (remote reads done); wait at the very end so
    // no CTA exits while a peer could still read its smem. Equal chunks => ~0 skew.
    asm volatile("barrier.cluster.arrive.aligned;" ::: "memory");

    // ---- pass 2: recompute (chunk is L2-resident) and scale ----
#pragma unroll 4
    for (int r = c_lo + (int)threadIdx.x; r < c_hi; r += BLOCK) {
        float4 v = x[r];
        float4 o;
        o.x = (v.x * w[0]  + v.y * w[1]  + v.z * w[2]  + v.w * w[3])  * inv;
        o.y = (v.x * w[4]  + v.y * w[5]  + v.z * w[6]  + v.w * w[7])  * inv;
        o.z = (v.x * w[8]  + v.y * w[9]  + v.z * w[10] + v.w * w[11]) * inv;
        o.w = (v.x * w[12] + v.y * w[13] + v.z * w[14] + v.w * w[15]) * inv;
        out[r] = o;
    }

    asm volatile("barrier.cluster.wait.aligned;" ::: "memory");
}

extern "C" void kernel_launch(void* const* d_in, const int* in_sizes, int n_in,
                              void* d_out, int out_size)
{
    const float4* x      = (const float4*)d_in[0];   // [N_ROWS, 4] fp32
    const int*    slices = (const int*)d_in[1];      // [nseg+1] int32
    const float*  W      = (const float*)d_in[2];    // [4, 4] fp32
    float4*       out    = (float4*)d_out;           // [N_ROWS, 4] fp32

    const int nseg = in_sizes[1] - 1;                // 4096
    seg_norm_cluster<<<nseg * SPLIT, BLOCK>>>(x, slices, W, out);
}

// round 4
// speedup vs baseline: 1.6732x; 1.5002x over previous
#include <cuda_runtime.h>

// Segment-normalized 4x4 linear: y = x @ W^T, then y /= sum(|y|) per segment.
//
// One CTA per segment, BLOCK=1024 threads (kills the long-segment straggler:
// 17k-row max segment -> ~17 iters/thread). Explicit 8-deep batched loads give
// MLP=8 per thread with no branches between loads. Pass 2 re-reads the CTA's
// chunk (L1-resident: avg 32KB, 2 CTAs/SM) and writes with streaming stores
// so `out` doesn't evict x. No cross-CTA sync of any kind.

#define BLOCK  1024
#define UNROLL 8

__device__ __forceinline__ float row_abs_sum(float4 v, const float* w)
{
    float y0 = v.x * w[0]  + v.y * w[1]  + v.z * w[2]  + v.w * w[3];
    float y1 = v.x * w[4]  + v.y * w[5]  + v.z * w[6]  + v.w * w[7];
    float y2 = v.x * w[8]  + v.y * w[9]  + v.z * w[10] + v.w * w[11];
    float y3 = v.x * w[12] + v.y * w[13] + v.z * w[14] + v.w * w[15];
    return fabsf(y0) + fabsf(y1) + fabsf(y2) + fabsf(y3);
}

__global__ __launch_bounds__(BLOCK)
void seg_norm_kernel(const float4* __restrict__ x,
                     const int*    __restrict__ slices,
                     const float*  __restrict__ W,
                     float4*       __restrict__ out)
{
    const int s  = blockIdx.x;
    const int lo = slices[s];
    const int hi = slices[s + 1];

    float w[16];
#pragma unroll
    for (int i = 0; i < 16; ++i) w[i] = __ldg(&W[i]);

    __shared__ float s_red[BLOCK / 32];
    __shared__ float s_inv;

    const int r0 = lo + (int)threadIdx.x;

    // ---- pass 1: sum of |y| over this CTA's segment ----
    float local = 0.0f;
    int r = r0;
    // main loop: 8 loads issued back-to-back (MLP=8), then compute
    while (r + (UNROLL - 1) * BLOCK < hi) {
        float4 v[UNROLL];
#pragma unroll
        for (int u = 0; u < UNROLL; ++u) v[u] = x[r + u * BLOCK];
#pragma unroll
        for (int u = 0; u < UNROLL; ++u) local += row_abs_sum(v[u], w);
        r += UNROLL * BLOCK;
    }
    for (; r < hi; r += BLOCK) local += row_abs_sum(x[r], w);

    // warp reduce
#pragma unroll
    for (int o = 16; o > 0; o >>= 1)
        local += __shfl_down_sync(0xFFFFFFFFu, local, o);

    const int lane = threadIdx.x & 31;
    const int warp = threadIdx.x >> 5;
    if (lane == 0) s_red[warp] = local;
    __syncthreads();

    if (threadIdx.x == 0) {
        float t = 0.0f;
#pragma unroll
        for (int i = 0; i < BLOCK / 32; ++i) t += s_red[i];
        s_inv = 1.0f / t;              // empty segment -> inf, but 0 rows written
    }
    __syncthreads();
    const float inv = s_inv;

    // ---- pass 2: recompute y (chunk is L1/L2-resident) and scale ----
    r = r0;
    while (r + (UNROLL - 1) * BLOCK < hi) {
        float4 v[UNROLL];
#pragma unroll
        for (int u = 0; u < UNROLL; ++u) v[u] = x[r + u * BLOCK];
#pragma unroll
        for (int u = 0; u < UNROLL; ++u) {
            float4 o;
            o.x = (v[u].x * w[0]  + v[u].y * w[1]  + v[u].z * w[2]  + v[u].w * w[3])  * inv;
            o.y = (v[u].x * w[4]  + v[u].y * w[5]  + v[u].z * w[6]  + v[u].w * w[7])  * inv;
            o.z = (v[u].x * w[8]  + v[u].y * w[9]  + v[u].z * w[10] + v[u].w * w[11]) * inv;
            o.w = (v[u].x * w[12] + v[u].y * w[13] + v[u].z * w[14] + v[u].w * w[15]) * inv;
            __stcs(&out[r + u * BLOCK], o);   // streaming: don't evict x
        }
        r += UNROLL * BLOCK;
    }
    for (; r < hi; r += BLOCK) {
        float4 v = x[r];
        float4 o;
        o.x = (v.x * w[0]  + v.y * w[1]  + v.z * w[2]  + v.w * w[3])  * inv;
        o.y = (v.x * w[4]  + v.y * w[5]  + v.z * w[6]  + v.w * w[7])  * inv;
        o.z = (v.x * w[8]  + v.y * w[9]  + v.z * w[10] + v.w * w[11]) * inv;
        o.w = (v.x * w[12] + v.y * w[13] + v.z * w[14] + v.w * w[15]) * inv;
        __stcs(&out[r], o);
    }
}

extern "C" void kernel_launch(void* const* d_in, const int* in_sizes, int n_in,
                              void* d_out, int out_size)
{
    const float4* x      = (const float4*)d_in[0];   // [N_ROWS, 4] fp32
    const int*    slices = (const int*)d_in[1];      // [nseg+1] int32
    const float*  W      = (const float*)d_in[2];    // [4, 4] fp32
    float4*       out    = (float4*)d_out;           // [N_ROWS, 4] fp32

    const int nseg = in_sizes[1] - 1;                // 4096
    seg_norm_kernel<<<nseg, BLOCK>>>(x, slices, W, out);
}

// round 9
// speedup vs baseline: 1.7066x; 1.0200x over previous
#include <cuda_runtime.h>

// Segment-normalized 4x4 linear: y = x @ W^T, then y /= sum(|y|) per segment.
//
// SYNC-FREE split scheme:
//   grid = (SPLIT, nseg). CTA (c, s) loads the segment bounds.
//   - len <= THRESH: chunk 0 handles the whole segment solo; chunks 1..3 exit.
//   - len >  THRESH: ALL chunks compute the FULL segment |y|-sum in pass 1
//     (identical thread mapping -> bit-identical sum; siblings are launch-
//     adjacent so redundant reads hit L1/L2), then each writes only its own
//     1/SPLIT slice in pass 2. No atomics, no barriers, no cross-CTA state.
// BLOCK=256 keeps 8+ CTAs/SM resident so small-segment latency overlaps.

#define BLOCK  256
#define SPLIT  4
#define THRESH 2048
#define UNROLL 4

__device__ __forceinline__ float row_abs_sum(float4 v, const float* w)
{
    float y0 = v.x * w[0]  + v.y * w[1]  + v.z * w[2]  + v.w * w[3];
    float y1 = v.x * w[4]  + v.y * w[5]  + v.z * w[6]  + v.w * w[7];
    float y2 = v.x * w[8]  + v.y * w[9]  + v.z * w[10] + v.w * w[11];
    float y3 = v.x * w[12] + v.y * w[13] + v.z * w[14] + v.w * w[15];
    return fabsf(y0) + fabsf(y1) + fabsf(y2) + fabsf(y3);
}

__global__ __launch_bounds__(BLOCK)
void seg_norm_kernel(const float4* __restrict__ x,
                     const int*    __restrict__ slices,
                     const float*  __restrict__ W,
                     float4*       __restrict__ out)
{
    const int c = blockIdx.x;                  // chunk id (launch-adjacent)
    const int s = blockIdx.y;                  // segment id

    const int lo  = __ldg(&slices[s]);
    const int hi  = __ldg(&slices[s + 1]);
    const int len = hi - lo;

    if (len <= THRESH && c != 0) return;       // solo segment: helpers bail

    float w[16];
#pragma unroll
    for (int i = 0; i < 16; ++i) w[i] = __ldg(&W[i]);

    __shared__ float s_red[BLOCK / 32];
    __shared__ float s_inv;

    // ---- pass 1: FULL-segment sum of |y| (identical across sibling chunks) ----
    float local = 0.0f;
    int r = lo + (int)threadIdx.x;
    while (r + (UNROLL - 1) * BLOCK < hi) {
        float4 v[UNROLL];
#pragma unroll
        for (int u = 0; u < UNROLL; ++u) v[u] = x[r + u * BLOCK];
#pragma unroll
        for (int u = 0; u < UNROLL; ++u) local += row_abs_sum(v[u], w);
        r += UNROLL * BLOCK;
    }
    for (; r < hi; r += BLOCK) local += row_abs_sum(x[r], w);

#pragma unroll
    for (int o = 16; o > 0; o >>= 1)
        local += __shfl_down_sync(0xFFFFFFFFu, local, o);

    const int lane = threadIdx.x & 31;
    const int warp = threadIdx.x >> 5;
    if (lane == 0) s_red[warp] = local;
    __syncthreads();

    if (threadIdx.x == 0) {
        float t = 0.0f;
#pragma unroll
        for (int i = 0; i < BLOCK / 32; ++i) t += s_red[i];
        s_inv = 1.0f / t;                      // empty segment -> 0 rows written
    }
    __syncthreads();
    const float inv = s_inv;

    // ---- pass 2: write this chunk's slice only ----
    int w_lo, w_hi;
    if (len <= THRESH) { w_lo = lo; w_hi = hi; }
    else {
        w_lo = lo + (len * c)       / SPLIT;
        w_hi = lo + (len * (c + 1)) / SPLIT;
    }

    r = w_lo + (int)threadIdx.x;
    while (r + (UNROLL - 1) * BLOCK < w_hi) {
        float4 v[UNROLL];
#pragma unroll
        for (int u = 0; u < UNROLL; ++u) v[u] = x[r + u * BLOCK];
#pragma unroll
        for (int u = 0; u < UNROLL; ++u) {
            float4 o;
            o.x = (v[u].x * w[0]  + v[u].y * w[1]  + v[u].z * w[2]  + v[u].w * w[3])  * inv;
            o.y = (v[u].x * w[4]  + v[u].y * w[5]  + v[u].z * w[6]  + v[u].w * w[7])  * inv;
            o.z = (v[u].x * w[8]  + v[u].y * w[9]  + v[u].z * w[10] + v[u].w * w[11]) * inv;
            o.w = (v[u].x * w[12] + v[u].y * w[13] + v[u].z * w[14] + v[u].w * w[15]) * inv;
            __stcs(&out[r + u * BLOCK], o);    // streaming store: don't evict x
        }
        r += UNROLL * BLOCK;
    }
    for (; r < w_hi; r += BLOCK) {
        float4 v = x[r];
        float4 o;
        o.x = (v.x * w[0]  + v.y * w[1]  + v.z * w[2]  + v.w * w[3])  * inv;
        o.y = (v.x * w[4]  + v.y * w[5]  + v.z * w[6]  + v.w * w[7])  * inv;
        o.z = (v.x * w[8]  + v.y * w[9]  + v.z * w[10] + v.w * w[11]) * inv;
        o.w = (v.x * w[12] + v.y * w[13] + v.z * w[14] + v.w * w[15]) * inv;
        __stcs(&out[r], o);
    }
}

extern "C" void kernel_launch(void* const* d_in, const int* in_sizes, int n_in,
                              void* d_out, int out_size)
{
    const float4* x      = (const float4*)d_in[0];   // [N_ROWS, 4] fp32
    const int*    slices = (const int*)d_in[1];      // [nseg+1] int32
    const float*  W      = (const float*)d_in[2];    // [4, 4] fp32
    float4*       out    = (float4*)d_out;           // [N_ROWS, 4] fp32

    const int nseg = in_sizes[1] - 1;                // 4096
    dim3 grid(SPLIT, nseg, 1);
    seg_norm_kernel<<<grid, BLOCK>>>(x, slices, W, out);
}